// round 14
// baseline (speedup 1.0000x reference)
#include <cuda_runtime.h>
#include <cuda_bf16.h>
#include <math.h>
#include <stdint.h>

// Problem constants
#define BATCH 8
#define DIM   64
#define HID   128
#define C2    256      // 2*HID
#define IMG_H 128
#define IMG_W 128
#define HW    16384    // 128*128

// Scratch u, INTERLEAVED: g_u2[b][cp][px] holds pair (u[cp], u[cp+128]).
__device__ float g_u2[(size_t)BATCH * HID * HW * 2];
// Scratch g = gelu(x1)*x2, planar (B, HID, HW) fp32 = 64 MiB.
__device__ float g_g[(size_t)BATCH * HID * HW];

// ---------------- packed f32x2 helpers (sm_103a FFMA2) ----------------
__device__ __forceinline__ unsigned long long pk2(float v) {
    unsigned long long r;
    asm("mov.b64 %0, {%1, %1};" : "=l"(r) : "f"(v));
    return r;
}
__device__ __forceinline__ unsigned long long fma2(unsigned long long a,
                                                   unsigned long long b,
                                                   unsigned long long c) {
    unsigned long long d;
    asm("fma.rn.f32x2 %0, %1, %2, %3;" : "=l"(d) : "l"(a), "l"(b), "l"(c));
    return d;
}
__device__ __forceinline__ void upk(unsigned long long v, float& lo, float& hi) {
    asm("mov.b64 {%0, %1}, %2;" : "=f"(lo), "=f"(hi) : "l"(v));
}

// ---------------- cp.async helpers ----------------
__device__ __forceinline__ void cp16(void* smem_dst, const void* gmem_src, int src_sz) {
    unsigned int s = (unsigned int)__cvta_generic_to_shared(smem_dst);
    asm volatile("cp.async.ca.shared.global [%0], [%1], 16, %2;\n"
                 :: "r"(s), "l"(gmem_src), "r"(src_sz));
}
__device__ __forceinline__ void cp_commit() {
    asm volatile("cp.async.commit_group;\n");
}
template <int N>
__device__ __forceinline__ void cp_wait() {
    asm volatile("cp.async.wait_group %0;\n" :: "n"(N));
}

// 16B-chunk XOR swizzles (conflict-free stride-32B/64B access)
__device__ __forceinline__ int swz4(int c) { return c ^ ((c >> 3) & 3); }  // 512B row
__device__ __forceinline__ int swz8(int c) { return c ^ ((c >> 3) & 7); }  // 1024B+ row
// SW128 byte swizzle for 128B-row k-major tiles (ldmatrix conflict-free)
#define SWZ128(o) ((o) ^ (((o) >> 3) & 0x70))

// ---------------- mma.sync (HMMA, plain sm_80+ PTX) ----------------
__device__ __forceinline__ void ldmx4(uint32_t* r, uint32_t a) {
    asm volatile("ldmatrix.sync.aligned.m8n8.x4.shared.b16 {%0,%1,%2,%3}, [%4];"
                 : "=r"(r[0]), "=r"(r[1]), "=r"(r[2]), "=r"(r[3]) : "r"(a));
}
__device__ __forceinline__ void ldmx2(uint32_t& r0, uint32_t& r1, uint32_t a) {
    asm volatile("ldmatrix.sync.aligned.m8n8.x2.shared.b16 {%0,%1}, [%2];"
                 : "=r"(r0), "=r"(r1) : "r"(a));
}
__device__ __forceinline__ void mma16816(float* d, const uint32_t* a,
                                         uint32_t b0, uint32_t b1) {
    asm volatile("mma.sync.aligned.m16n8k16.row.col.f32.bf16.bf16.f32 "
                 "{%0,%1,%2,%3}, {%4,%5,%6,%7}, {%8,%9}, {%0,%1,%2,%3};"
                 : "+f"(d[0]), "+f"(d[1]), "+f"(d[2]), "+f"(d[3])
                 : "r"(a[0]), "r"(a[1]), "r"(a[2]), "r"(a[3]), "r"(b0), "r"(b1));
}

// bf16 hi/lo split of two floats, packed (v0 low half-word, v1 high)
__device__ __forceinline__ void bsplit2(float v0, float v1, uint32_t& h, uint32_t& l) {
    __nv_bfloat16 h0 = __float2bfloat16(v0), h1 = __float2bfloat16(v1);
    float r0 = v0 - __bfloat162float(h0);
    float r1 = v1 - __bfloat162float(h1);
    __nv_bfloat16 l0 = __float2bfloat16(r0), l1 = __float2bfloat16(r1);
    unsigned short uh0 = *reinterpret_cast<unsigned short*>(&h0);
    unsigned short uh1 = *reinterpret_cast<unsigned short*>(&h1);
    unsigned short ul0 = *reinterpret_cast<unsigned short*>(&l0);
    unsigned short ul1 = *reinterpret_cast<unsigned short*>(&l1);
    h = ((uint32_t)uh1 << 16) | uh0;
    l = ((uint32_t)ul1 << 16) | ul0;
}

// =====================================================================
// Kernel 1 (HMMA): u = W_in * x via bf16x3 split mma.sync.
// CTA = 128 px x 128 ch-half (blockIdx.y: rows 0-63 = ch cp0p..cp0p+63,
// rows 64-127 = ch 128+cp0p..), 256 threads = 8 warps.
// A = W [128 rows x 64 k] bf16 hi/lo, SW128 k-major.  B = x^T [128 px
// rows x 64 k] hi/lo, same layout (transposed via planar SMEM tile).
// Warp w: M-tile rows 16w..16w+15, all 128 px: 16 n-tiles x 4 k-steps
// x 3 splits = 192 mma.  Epilogue: SMEM transpose -> interleaved g_u2.
// =====================================================================
#define K1_XS 0                   // 32 KB planar f32 [64 k][128 px]; reused as epi buf
#define K1_AH 32768
#define K1_AL 49152
#define K1_BH 65536
#define K1_BL 81920
#define K1_SMEM 98304

__global__ void __launch_bounds__(256, 2)
k_proj_in_mma(const float* __restrict__ x, const float* __restrict__ W_in) {
    extern __shared__ char sm1[];
    float* xs = (float*)sm1;
    const uint32_t sb = (uint32_t)__cvta_generic_to_shared(sm1);
    const int t   = threadIdx.x;
    const int w   = t >> 5;
    const int lid = t & 31;
    const int b   = blockIdx.z;
    const int cp0p = blockIdx.y * 64;
    const int p0  = blockIdx.x * 128;

    // ---- stage x planar (coalesced cp.async): 64 k x 32 chunks ----
    const float* xg = x + ((size_t)b * DIM) * HW + p0;
#pragma unroll
    for (int i = 0; i < 8; i++) {
        int idx = t + i * 256;
        int kk = idx >> 5, c4 = idx & 31;
        cp16(&xs[idx * 4], xg + (size_t)kk * HW + c4 * 4, 16);
    }
    cp_commit();

    // ---- stage W split hi/lo (SW128 k-major rows) ----
    const int row  = t >> 1;
    const int koff = (t & 1) * 32;
    {
        int ch = (row < 64) ? (cp0p + row) : (128 + cp0p + row - 64);
        const float4* wr = (const float4*)&W_in[ch * 64 + koff];
#pragma unroll
        for (int c4 = 0; c4 < 4; c4++) {
            float4 v0 = wr[2 * c4], v1 = wr[2 * c4 + 1];
            uint4 hq, lq;
            bsplit2(v0.x, v0.y, hq.x, lq.x);
            bsplit2(v0.z, v0.w, hq.y, lq.y);
            bsplit2(v1.x, v1.y, hq.z, lq.z);
            bsplit2(v1.z, v1.w, hq.w, lq.w);
            int off = row * 128 + koff * 2 + c4 * 16;
            *(uint4*)(sm1 + K1_AH + SWZ128(off)) = hq;
            *(uint4*)(sm1 + K1_AL + SWZ128(off)) = lq;
        }
    }
    cp_wait<0>();
    __syncthreads();

    // ---- transpose x -> B^T split hi/lo ----
    {
        int px = t >> 1;
#pragma unroll
        for (int c4 = 0; c4 < 4; c4++) {
            float v[8];
#pragma unroll
            for (int j = 0; j < 8; j++) v[j] = xs[(koff + c4 * 8 + j) * 128 + px];
            uint4 hq, lq;
            bsplit2(v[0], v[1], hq.x, lq.x);
            bsplit2(v[2], v[3], hq.y, lq.y);
            bsplit2(v[4], v[5], hq.z, lq.z);
            bsplit2(v[6], v[7], hq.w, lq.w);
            int off = px * 128 + koff * 2 + c4 * 16;
            *(uint4*)(sm1 + K1_BH + SWZ128(off)) = hq;
            *(uint4*)(sm1 + K1_BL + SWZ128(off)) = lq;
        }
    }
    __syncthreads();

    // ---- A fragments (8 ldmatrix.x4, kept in registers) ----
    uint32_t afh[4][4], afl[4][4];
    {
        int mrow = 16 * w + (lid & 15);
        int hi16 = (lid >> 4) * 16;
#pragma unroll
        for (int ks = 0; ks < 4; ks++) {
            ldmx4(afh[ks], sb + K1_AH + SWZ128(mrow * 128 + ks * 32 + hi16));
            ldmx4(afl[ks], sb + K1_AL + SWZ128(mrow * 128 + ks * 32 + hi16));
        }
    }

    // ---- main: 16 n-tiles x 4 k-steps x 3 split-mma ----
    float acc[16][4];
#pragma unroll
    for (int i = 0; i < 16; i++)
#pragma unroll
        for (int j = 0; j < 4; j++) acc[i][j] = 0.0f;

    const int nrow  = lid & 7;
    const int sel16 = ((lid >> 3) & 1) * 16;
#pragma unroll 4
    for (int nt = 0; nt < 16; nt++) {
        int base = (8 * nt + nrow) * 128;
#pragma unroll
        for (int ks = 0; ks < 4; ks++) {
            uint32_t bh0, bh1, bl0, bl1;
            ldmx2(bh0, bh1, sb + K1_BH + SWZ128(base + ks * 32 + sel16));
            ldmx2(bl0, bl1, sb + K1_BL + SWZ128(base + ks * 32 + sel16));
            mma16816(acc[nt], afh[ks], bh0, bh1);   // Wh * xh
            mma16816(acc[nt], afh[ks], bl0, bl1);   // Wh * xl
            mma16816(acc[nt], afl[ks], bh0, bh1);   // Wl * xh
        }
    }

    // ---- epilogue: 4 px-chunks of 32, SMEM transpose (reuse xs) ----
    float* buf = xs;                       // [128 rows][34 stride]
    const int g  = lid >> 2;
    const int tt = lid & 3;
    const int cpl = t >> 2;
    const int px8 = (t & 3) * 8;
#pragma unroll 1
    for (int c = 0; c < 4; c++) {
        __syncthreads();                   // prior reads of buf complete
#pragma unroll
        for (int j = 0; j < 4; j++) {
            int nt  = 4 * c + j;
            int pxl = 8 * j + 2 * tt;
            *(float2*)&buf[(16 * w + g) * 34 + pxl]     = make_float2(acc[nt][0], acc[nt][1]);
            *(float2*)&buf[(16 * w + g + 8) * 34 + pxl] = make_float2(acc[nt][2], acc[nt][3]);
        }
        __syncthreads();
#pragma unroll
        for (int i = 0; i < 8; i++) {
            float av = buf[cpl * 34 + px8 + i];
            float bv = buf[(cpl + 64) * 34 + px8 + i];
            *(float2*)(g_u2 + (((size_t)b * HID + cp0p + cpl) * HW + p0 + c * 32 + px8 + i) * 2) =
                make_float2(av, bv);
        }
    }
}

// =====================================================================
// Kernel 2a: dynamic depthwise 3x3 + exact GELU gate -> g (planar).
// (unchanged — passing, swizzled, conflict-free)
// =====================================================================
#define AROW 264
__global__ void __launch_bounds__(256) k_conv_gelu(const float* __restrict__ genk,
                                                   const float* __restrict__ dwkg,
                                                   const float* __restrict__ lam) {
    __shared__ float halo[34 * AROW];     // 35904 B
    __shared__ float kc2s[18];

    const int t  = threadIdx.x;
    const int cp = blockIdx.x;            // channel pair 0..127
    const int rb = blockIdx.y;            // row block 0..3
    const int b  = blockIdx.z;
    const int y0 = rb * 32;

    if (t < 18) {
        int tap = t >> 1, br = t & 1;
        int c = cp + br * HID;
        kc2s[tap * 2 + br] = dwkg[c * 9 + tap] + lam[c] * genk[b * (C2 * 9) + c * 9 + tap];
    }
    for (int i = t; i < 272; i += 256) {
        int rr = i >> 3, j = i & 7;
        halo[rr * AROW + ((j < 4) ? j : (256 + j))] = 0.0f;
    }
    {
        const float* src0 = g_u2 + ((size_t)b * HID + cp) * HW * 2;
#pragma unroll
        for (int i = 0; i < 9; i++) {
            int idx = t + i * 256;
            if (idx < 2176) {
                int rr = idx >> 6, ch = idx & 63;
                int gy = y0 - 1 + rr;
                bool ok = (unsigned)gy < 128u;
                cp16(&halo[rr * AROW + swz8(1 + ch) * 4],
                     src0 + (size_t)(ok ? gy : 0) * 256 + ch * 4, ok ? 16 : 0);
            }
        }
        cp_commit();
    }
    cp_wait<0>();
    __syncthreads();

    unsigned long long tap[9];
#pragma unroll
    for (int i = 0; i < 9; i++) tap[i] = *(const unsigned long long*)&kc2s[2 * i];

    const int s  = t & 15;
    const int x0 = s * 8;
    const int yb = t >> 4;
    int qof[6];
#pragma unroll
    for (int j = 0; j < 6; j++) qof[j] = swz8(4 * s + j) * 4;

    float* gbase = g_g + ((size_t)b * HID + cp) * HW;

#pragma unroll
    for (int half = 0; half < 2; half++) {
        int y = yb + half * 16;
        unsigned long long v[8];
#pragma unroll
        for (int j = 0; j < 8; j++) v[j] = 0ull;

#pragma unroll
        for (int r = 0; r < 3; r++) {
            const float* Hrow = &halo[(y + r) * AROW];
            unsigned long long p[12];
#pragma unroll
            for (int j = 0; j < 6; j++) {
                ulonglong2 qq = *(const ulonglong2*)&Hrow[qof[j]];
                p[2 * j]     = qq.x;
                p[2 * j + 1] = qq.y;
            }
#pragma unroll
            for (int dx = 0; dx < 3; dx++) {
                unsigned long long tp_ = tap[r * 3 + dx];
#pragma unroll
                for (int j = 0; j < 8; j++)
                    v[j] = fma2(tp_, p[j + dx + 1], v[j]);
            }
        }
        float o8[8];
#pragma unroll
        for (int j = 0; j < 8; j++) {
            float va, vb;
            upk(v[j], va, vb);
            o8[j] = 0.5f * va * (1.0f + erff(va * 0.7071067811865476f)) * vb;
        }
        float* dst = gbase + (y0 + y) * IMG_W + x0;
        *(float4*)dst       = make_float4(o8[0], o8[1], o8[2], o8[3]);
        *(float4*)(dst + 4) = make_float4(o8[4], o8[5], o8[6], o8[7]);
    }
}

// =====================================================================
// Kernel 2b: out[b,o,p] = sum_c W_out[o,c] * g[b,c,p]
// (unchanged — double-buffered pipeline, unduplicated weights)
// =====================================================================
__global__ void __launch_bounds__(256, 2) k_proj_out(const float* __restrict__ W_out,
                                                     float* __restrict__ out) {
    extern __shared__ float smem2[];
    float* gsT = smem2;            // [2][32*256 swizzled]  65536 B
    float* Wo  = smem2 + 16384;    // [2][32*64]            16384 B

    const int t  = threadIdx.x;
    const int b  = blockIdx.z;
    const int p0 = blockIdx.x * 256;

    const int tx = t & 31;
    const int ty = t >> 5;
    const int pb = tx * 8;
    const int ob = ty * 8;
    const int q0 = swz8(2 * tx) * 4;
    const int q1 = swz8(2 * tx + 1) * 4;

    const float* gb = g_g + ((size_t)b * HID) * HW;

    auto stage_g = [&](int ph, int buf) {
        float* dstb = gsT + buf * 8192;
#pragma unroll
        for (int i = 0; i < 8; i++) {
            int idx = t + i * 256;
            int kk = idx >> 6, ch = idx & 63;
            cp16(&dstb[(kk * 64 + swz8(ch)) * 4],
                 gb + (size_t)(ph * 32 + kk) * HW + p0 + ch * 4, 16);
        }
        cp_commit();
    };
    auto w_ldg = [&](int ph, float* w8) {
#pragma unroll
        for (int i = 0; i < 8; i++) {
            int idx = t + i * 256;
            int kk = idx >> 6, o = idx & 63;
            w8[i] = W_out[o * HID + ph * 32 + kk];
        }
    };
    auto w_sts = [&](int buf, const float* w8) {
        float* dstb = Wo + buf * 2048;
#pragma unroll
        for (int i = 0; i < 8; i++) {
            int idx = t + i * 256;
            int kk = idx >> 6, o = idx & 63;
            dstb[kk * 64 + o] = w8[i];
        }
    };

    unsigned long long acc[8][4];
#pragma unroll
    for (int i = 0; i < 8; i++)
#pragma unroll
        for (int j = 0; j < 4; j++) acc[i][j] = 0ull;

    float wreg[8];
    stage_g(0, 0);
    w_ldg(0, wreg);
    w_sts(0, wreg);
    cp_wait<0>();
    __syncthreads();

#pragma unroll 1
    for (int ph = 0; ph < 4; ph++) {
        const int buf = ph & 1;
        if (ph < 3) {
            stage_g(ph + 1, buf ^ 1);
            w_ldg(ph + 1, wreg);
        }

        const float* gB = gsT + buf * 8192;
        const float* wB = Wo + buf * 2048;
#pragma unroll 8
        for (int kk = 0; kk < 32; kk++) {
            float4 w0 = *(const float4*)&wB[kk * 64 + ob];
            float4 w1 = *(const float4*)&wB[kk * 64 + ob + 4];
            ulonglong2 gA  = *(const ulonglong2*)&gB[kk * 256 + q0];
            ulonglong2 gBv = *(const ulonglong2*)&gB[kk * 256 + q1];
            unsigned long long wp0 = pk2(w0.x), wp1 = pk2(w0.y),
                               wp2 = pk2(w0.z), wp3 = pk2(w0.w),
                               wp4 = pk2(w1.x), wp5 = pk2(w1.y),
                               wp6 = pk2(w1.z), wp7 = pk2(w1.w);

            acc[0][0] = fma2(wp0, gA.x, acc[0][0]);
            acc[0][1] = fma2(wp0, gA.y, acc[0][1]);
            acc[0][2] = fma2(wp0, gBv.x, acc[0][2]);
            acc[0][3] = fma2(wp0, gBv.y, acc[0][3]);
            acc[1][0] = fma2(wp1, gA.x, acc[1][0]);
            acc[1][1] = fma2(wp1, gA.y, acc[1][1]);
            acc[1][2] = fma2(wp1, gBv.x, acc[1][2]);
            acc[1][3] = fma2(wp1, gBv.y, acc[1][3]);
            acc[2][0] = fma2(wp2, gA.x, acc[2][0]);
            acc[2][1] = fma2(wp2, gA.y, acc[2][1]);
            acc[2][2] = fma2(wp2, gBv.x, acc[2][2]);
            acc[2][3] = fma2(wp2, gBv.y, acc[2][3]);
            acc[3][0] = fma2(wp3, gA.x, acc[3][0]);
            acc[3][1] = fma2(wp3, gA.y, acc[3][1]);
            acc[3][2] = fma2(wp3, gBv.x, acc[3][2]);
            acc[3][3] = fma2(wp3, gBv.y, acc[3][3]);
            acc[4][0] = fma2(wp4, gA.x, acc[4][0]);
            acc[4][1] = fma2(wp4, gA.y, acc[4][1]);
            acc[4][2] = fma2(wp4, gBv.x, acc[4][2]);
            acc[4][3] = fma2(wp4, gBv.y, acc[4][3]);
            acc[5][0] = fma2(wp5, gA.x, acc[5][0]);
            acc[5][1] = fma2(wp5, gA.y, acc[5][1]);
            acc[5][2] = fma2(wp5, gBv.x, acc[5][2]);
            acc[5][3] = fma2(wp5, gBv.y, acc[5][3]);
            acc[6][0] = fma2(wp6, gA.x, acc[6][0]);
            acc[6][1] = fma2(wp6, gA.y, acc[6][1]);
            acc[6][2] = fma2(wp6, gBv.x, acc[6][2]);
            acc[6][3] = fma2(wp6, gBv.y, acc[6][3]);
            acc[7][0] = fma2(wp7, gA.x, acc[7][0]);
            acc[7][1] = fma2(wp7, gA.y, acc[7][1]);
            acc[7][2] = fma2(wp7, gBv.x, acc[7][2]);
            acc[7][3] = fma2(wp7, gBv.y, acc[7][3]);
        }

        if (ph < 3) {
            w_sts(buf ^ 1, wreg);
            cp_wait<0>();
            __syncthreads();
        }
    }

#pragma unroll
    for (int oi = 0; oi < 8; oi++) {
        float* dst = out + ((size_t)b * DIM + (ob + oi)) * HW + p0 + pb;
        ulonglong2 v0, v1;
        v0.x = acc[oi][0]; v0.y = acc[oi][1];
        v1.x = acc[oi][2]; v1.y = acc[oi][3];
        ((ulonglong2*)dst)[0] = v0;
        ((ulonglong2*)dst)[1] = v1;
    }
}

// =====================================================================
// Launch (graph-capturable, no allocs)
// Inputs: x, gen_kernel, W_in, dw_kernel, lambda_dw, W_out
// =====================================================================
extern "C" void kernel_launch(void* const* d_in, const int* in_sizes, int n_in,
                              void* d_out, int out_size) {
    const float* x     = (const float*)d_in[0];
    const float* genk  = (const float*)d_in[1];
    const float* W_in  = (const float*)d_in[2];
    const float* dwk   = (const float*)d_in[3];
    const float* lam   = (const float*)d_in[4];
    const float* W_out = (const float*)d_in[5];
    float* out = (float*)d_out;

    static int attr_done = 0;
    if (!attr_done) {
        cudaFuncSetAttribute(k_proj_in_mma, cudaFuncAttributeMaxDynamicSharedMemorySize, K1_SMEM);
        cudaFuncSetAttribute(k_proj_out,    cudaFuncAttributeMaxDynamicSharedMemorySize, 81920);
        attr_done = 1;
    }

    dim3 g1(HW / 128, 2, BATCH);            // (128, 2, 8)
    k_proj_in_mma<<<g1, 256, K1_SMEM>>>(x, W_in);

    dim3 g2(HID, IMG_H / 32, BATCH);        // (128, 4, 8)
    k_conv_gelu<<<g2, 256>>>(genk, dwk, lam);

    dim3 g3(HW / 256, 1, BATCH);            // (64, 1, 8)
    k_proj_out<<<g3, 256, 81920>>>(W_out, out);
}

// round 15
// speedup vs baseline: 1.0319x; 1.0319x over previous
#include <cuda_runtime.h>
#include <math.h>

// Problem constants
#define BATCH 8
#define DIM   64
#define HID   128
#define C2    256      // 2*HID
#define IMG_H 128
#define IMG_W 128
#define HW    16384    // 128*128

// Scratch u, INTERLEAVED: g_u2[b][cp][px] holds pair (u[cp], u[cp+128]).
__device__ float g_u2[(size_t)BATCH * HID * HW * 2];
// Scratch g = gelu(x1)*x2, planar (B, HID, HW) fp32 = 64 MiB.
__device__ float g_g[(size_t)BATCH * HID * HW];

// ---------------- packed f32x2 helpers (sm_103a FFMA2) ----------------
__device__ __forceinline__ unsigned long long pk2(float v) {
    unsigned long long r;
    asm("mov.b64 %0, {%1, %1};" : "=l"(r) : "f"(v));
    return r;
}
__device__ __forceinline__ unsigned long long fma2(unsigned long long a,
                                                   unsigned long long b,
                                                   unsigned long long c) {
    unsigned long long d;
    asm("fma.rn.f32x2 %0, %1, %2, %3;" : "=l"(d) : "l"(a), "l"(b), "l"(c));
    return d;
}
__device__ __forceinline__ void upk(unsigned long long v, float& lo, float& hi) {
    asm("mov.b64 {%0, %1}, %2;" : "=f"(lo), "=f"(hi) : "l"(v));
}

// ---------------- cp.async helpers ----------------
__device__ __forceinline__ void cp16(void* smem_dst, const void* gmem_src, int src_sz) {
    unsigned int s = (unsigned int)__cvta_generic_to_shared(smem_dst);
    asm volatile("cp.async.ca.shared.global [%0], [%1], 16, %2;\n"
                 :: "r"(s), "l"(gmem_src), "r"(src_sz));
}
__device__ __forceinline__ void cp_commit() {
    asm volatile("cp.async.commit_group;\n");
}
template <int N>
__device__ __forceinline__ void cp_wait() {
    asm volatile("cp.async.wait_group %0;\n" :: "n"(N));
}

// 16B-chunk XOR swizzles (conflict-free stride-32B/64B access)
__device__ __forceinline__ int swz4(int c) { return c ^ ((c >> 3) & 3); }  // 512B row
__device__ __forceinline__ int swz8(int c) { return c ^ ((c >> 3) & 7); }  // 1024B+ row

// =====================================================================
// Kernel 1 (round-12 SIMT, per-batch): u = W_in * x, interleaved store.
// FULL-K prefetch, unduplicated weights, single barrier.
// =====================================================================
__global__ void __launch_bounds__(256, 2) k_proj_in(const float* __restrict__ x,
                                                    const float* __restrict__ W_in,
                                                    int b) {
    extern __shared__ float smem1[];
    float* xs  = smem1;            // [64][128 swizzled]  32768 B
    float* Wsa = smem1 + 8192;     // [64][64]            16384 B
    float* Wsb = smem1 + 12288;    // [64][64]            16384 B

    const int t   = threadIdx.x;
    const int cp0 = blockIdx.y * 64;
    const int p0  = blockIdx.x * 128;

    const int tx = t & 15;
    const int ty = t >> 4;
    const int pb = tx * 8;
    const int q0 = swz4(2 * tx) * 4;
    const int q1 = swz4(2 * tx + 1) * 4;

    // ---- prologue: weight LDGs first (latency overlaps cp.async issue) ----
    float4 wva[4], wvb[4];
#pragma unroll
    for (int i = 0; i < 4; i++) {
        int idx = t + i * 256;            // 0..1023
        int j   = idx & 63;               // channel slot
        int kq  = idx >> 6;               // 0..15 (4 k each)
        wva[i] = *(const float4*)&W_in[(cp0 + j) * 64 + kq * 4];
        wvb[i] = *(const float4*)&W_in[(cp0 + 128 + j) * 64 + kq * 4];
    }
    const float* xg = x + ((size_t)b * DIM) * HW + p0;
#pragma unroll
    for (int i = 0; i < 8; i++) {
        int idx = t + i * 256;
        int kk  = idx >> 5;
        int c4  = idx & 31;
        cp16(&xs[(kk * 32 + swz4(c4)) * 4], xg + (size_t)kk * HW + c4 * 4, 16);
    }
    cp_commit();
#pragma unroll
    for (int i = 0; i < 4; i++) {
        int idx = t + i * 256;
        int j   = idx & 63;
        int kq  = idx >> 6;
        Wsa[(kq * 4 + 0) * 64 + j] = wva[i].x;
        Wsa[(kq * 4 + 1) * 64 + j] = wva[i].y;
        Wsa[(kq * 4 + 2) * 64 + j] = wva[i].z;
        Wsa[(kq * 4 + 3) * 64 + j] = wva[i].w;
        Wsb[(kq * 4 + 0) * 64 + j] = wvb[i].x;
        Wsb[(kq * 4 + 1) * 64 + j] = wvb[i].y;
        Wsb[(kq * 4 + 2) * 64 + j] = wvb[i].z;
        Wsb[(kq * 4 + 3) * 64 + j] = wvb[i].w;
    }
    cp_wait<0>();
    __syncthreads();                      // the ONLY barrier

    unsigned long long aa[4][4], ab[4][4];
#pragma unroll
    for (int i = 0; i < 4; i++)
#pragma unroll
        for (int j = 0; j < 4; j++) { aa[i][j] = 0ull; ab[i][j] = 0ull; }

#pragma unroll 8
    for (int kk = 0; kk < 64; kk++) {
        float4 wa = *(const float4*)&Wsa[kk * 64 + 4 * ty];
        float4 wb = *(const float4*)&Wsb[kk * 64 + 4 * ty];
        ulonglong2 xv0 = *(const ulonglong2*)(xs + kk * 128 + q0);
        ulonglong2 xv1 = *(const ulonglong2*)(xs + kk * 128 + q1);
        unsigned long long wa0 = pk2(wa.x), wa1 = pk2(wa.y),
                           wa2 = pk2(wa.z), wa3 = pk2(wa.w);
        unsigned long long wb0 = pk2(wb.x), wb1 = pk2(wb.y),
                           wb2 = pk2(wb.z), wb3 = pk2(wb.w);

        aa[0][0] = fma2(wa0, xv0.x, aa[0][0]);
        aa[0][1] = fma2(wa0, xv0.y, aa[0][1]);
        aa[0][2] = fma2(wa0, xv1.x, aa[0][2]);
        aa[0][3] = fma2(wa0, xv1.y, aa[0][3]);
        aa[1][0] = fma2(wa1, xv0.x, aa[1][0]);
        aa[1][1] = fma2(wa1, xv0.y, aa[1][1]);
        aa[1][2] = fma2(wa1, xv1.x, aa[1][2]);
        aa[1][3] = fma2(wa1, xv1.y, aa[1][3]);
        aa[2][0] = fma2(wa2, xv0.x, aa[2][0]);
        aa[2][1] = fma2(wa2, xv0.y, aa[2][1]);
        aa[2][2] = fma2(wa2, xv1.x, aa[2][2]);
        aa[2][3] = fma2(wa2, xv1.y, aa[2][3]);
        aa[3][0] = fma2(wa3, xv0.x, aa[3][0]);
        aa[3][1] = fma2(wa3, xv0.y, aa[3][1]);
        aa[3][2] = fma2(wa3, xv1.x, aa[3][2]);
        aa[3][3] = fma2(wa3, xv1.y, aa[3][3]);

        ab[0][0] = fma2(wb0, xv0.x, ab[0][0]);
        ab[0][1] = fma2(wb0, xv0.y, ab[0][1]);
        ab[0][2] = fma2(wb0, xv1.x, ab[0][2]);
        ab[0][3] = fma2(wb0, xv1.y, ab[0][3]);
        ab[1][0] = fma2(wb1, xv0.x, ab[1][0]);
        ab[1][1] = fma2(wb1, xv0.y, ab[1][1]);
        ab[1][2] = fma2(wb1, xv1.x, ab[1][2]);
        ab[1][3] = fma2(wb1, xv1.y, ab[1][3]);
        ab[2][0] = fma2(wb2, xv0.x, ab[2][0]);
        ab[2][1] = fma2(wb2, xv0.y, ab[2][1]);
        ab[2][2] = fma2(wb2, xv1.x, ab[2][2]);
        ab[2][3] = fma2(wb2, xv1.y, ab[2][3]);
        ab[3][0] = fma2(wb3, xv0.x, ab[3][0]);
        ab[3][1] = fma2(wb3, xv0.y, ab[3][1]);
        ab[3][2] = fma2(wb3, xv1.x, ab[3][2]);
        ab[3][3] = fma2(wb3, xv1.y, ab[3][3]);
    }

#pragma unroll
    for (int ci = 0; ci < 4; ci++) {
        int cp = cp0 + 4 * ty + ci;
        float* base = g_u2 + (((size_t)b * HID + cp) * HW + p0 + pb) * 2;
#pragma unroll
        for (int j = 0; j < 4; j++) {
            float alo, ahi, blo, bhi;
            upk(aa[ci][j], alo, ahi);
            upk(ab[ci][j], blo, bhi);
            *(float4*)(base + 4 * j) = make_float4(alo, blo, ahi, bhi);
        }
    }
}

// =====================================================================
// Kernel 2a: dynamic depthwise 3x3 + exact GELU gate -> g (planar).
// (round-12 code, per-batch)
// =====================================================================
#define AROW 264
__global__ void __launch_bounds__(256) k_conv_gelu(const float* __restrict__ genk,
                                                   const float* __restrict__ dwkg,
                                                   const float* __restrict__ lam,
                                                   int b) {
    __shared__ float halo[34 * AROW];     // 35904 B
    __shared__ float kc2s[18];

    const int t  = threadIdx.x;
    const int cp = blockIdx.x;            // channel pair 0..127
    const int rb = blockIdx.y;            // row block 0..3
    const int y0 = rb * 32;

    if (t < 18) {
        int tap = t >> 1, br = t & 1;
        int c = cp + br * HID;
        kc2s[tap * 2 + br] = dwkg[c * 9 + tap] + lam[c] * genk[b * (C2 * 9) + c * 9 + tap];
    }
    for (int i = t; i < 272; i += 256) {
        int rr = i >> 3, j = i & 7;
        halo[rr * AROW + ((j < 4) ? j : (256 + j))] = 0.0f;
    }
    {
        const float* src0 = g_u2 + ((size_t)b * HID + cp) * HW * 2;
#pragma unroll
        for (int i = 0; i < 9; i++) {
            int idx = t + i * 256;
            if (idx < 2176) {
                int rr = idx >> 6, ch = idx & 63;
                int gy = y0 - 1 + rr;
                bool ok = (unsigned)gy < 128u;
                cp16(&halo[rr * AROW + swz8(1 + ch) * 4],
                     src0 + (size_t)(ok ? gy : 0) * 256 + ch * 4, ok ? 16 : 0);
            }
        }
        cp_commit();
    }
    cp_wait<0>();
    __syncthreads();

    unsigned long long tap[9];
#pragma unroll
    for (int i = 0; i < 9; i++) tap[i] = *(const unsigned long long*)&kc2s[2 * i];

    const int s  = t & 15;
    const int x0 = s * 8;
    const int yb = t >> 4;
    int qof[6];
#pragma unroll
    for (int j = 0; j < 6; j++) qof[j] = swz8(4 * s + j) * 4;

    float* gbase = g_g + ((size_t)b * HID + cp) * HW;

#pragma unroll
    for (int half = 0; half < 2; half++) {
        int y = yb + half * 16;
        unsigned long long v[8];
#pragma unroll
        for (int j = 0; j < 8; j++) v[j] = 0ull;

#pragma unroll
        for (int r = 0; r < 3; r++) {
            const float* Hrow = &halo[(y + r) * AROW];
            unsigned long long p[12];
#pragma unroll
            for (int j = 0; j < 6; j++) {
                ulonglong2 qq = *(const ulonglong2*)&Hrow[qof[j]];
                p[2 * j]     = qq.x;
                p[2 * j + 1] = qq.y;
            }
#pragma unroll
            for (int dx = 0; dx < 3; dx++) {
                unsigned long long tp_ = tap[r * 3 + dx];
#pragma unroll
                for (int j = 0; j < 8; j++)
                    v[j] = fma2(tp_, p[j + dx + 1], v[j]);
            }
        }
        float o8[8];
#pragma unroll
        for (int j = 0; j < 8; j++) {
            float va, vb;
            upk(v[j], va, vb);
            o8[j] = 0.5f * va * (1.0f + erff(va * 0.7071067811865476f)) * vb;
        }
        float* dst = gbase + (y0 + y) * IMG_W + x0;
        *(float4*)dst       = make_float4(o8[0], o8[1], o8[2], o8[3]);
        *(float4*)(dst + 4) = make_float4(o8[4], o8[5], o8[6], o8[7]);
    }
}

// =====================================================================
// Kernel 2b: out[b,o,p] = sum_c W_out[o,c] * g[b,c,p]
// (round-12 code, per-batch; double-buffered pipeline)
// =====================================================================
__global__ void __launch_bounds__(256, 2) k_proj_out(const float* __restrict__ W_out,
                                                     float* __restrict__ out,
                                                     int b) {
    extern __shared__ float smem2[];
    float* gsT = smem2;            // [2][32*256 swizzled]  65536 B
    float* Wo  = smem2 + 16384;    // [2][32*64]            16384 B

    const int t  = threadIdx.x;
    const int p0 = blockIdx.x * 256;

    const int tx = t & 31;
    const int ty = t >> 5;
    const int pb = tx * 8;
    const int ob = ty * 8;
    const int q0 = swz8(2 * tx) * 4;
    const int q1 = swz8(2 * tx + 1) * 4;

    const float* gb = g_g + ((size_t)b * HID) * HW;

    auto stage_g = [&](int ph, int buf) {
        float* dstb = gsT + buf * 8192;
#pragma unroll
        for (int i = 0; i < 8; i++) {
            int idx = t + i * 256;
            int kk = idx >> 6, ch = idx & 63;
            cp16(&dstb[(kk * 64 + swz8(ch)) * 4],
                 gb + (size_t)(ph * 32 + kk) * HW + p0 + ch * 4, 16);
        }
        cp_commit();
    };
    auto w_ldg = [&](int ph, float* w8) {
#pragma unroll
        for (int i = 0; i < 8; i++) {
            int idx = t + i * 256;
            int kk = idx >> 6, o = idx & 63;
            w8[i] = W_out[o * HID + ph * 32 + kk];
        }
    };
    auto w_sts = [&](int buf, const float* w8) {
        float* dstb = Wo + buf * 2048;
#pragma unroll
        for (int i = 0; i < 8; i++) {
            int idx = t + i * 256;
            int kk = idx >> 6, o = idx & 63;
            dstb[kk * 64 + o] = w8[i];
        }
    };

    unsigned long long acc[8][4];
#pragma unroll
    for (int i = 0; i < 8; i++)
#pragma unroll
        for (int j = 0; j < 4; j++) acc[i][j] = 0ull;

    float wreg[8];
    stage_g(0, 0);
    w_ldg(0, wreg);
    w_sts(0, wreg);
    cp_wait<0>();
    __syncthreads();

#pragma unroll 1
    for (int ph = 0; ph < 4; ph++) {
        const int buf = ph & 1;
        if (ph < 3) {
            stage_g(ph + 1, buf ^ 1);
            w_ldg(ph + 1, wreg);
        }

        const float* gB = gsT + buf * 8192;
        const float* wB = Wo + buf * 2048;
#pragma unroll 8
        for (int kk = 0; kk < 32; kk++) {
            float4 w0 = *(const float4*)&wB[kk * 64 + ob];
            float4 w1 = *(const float4*)&wB[kk * 64 + ob + 4];
            ulonglong2 gA  = *(const ulonglong2*)&gB[kk * 256 + q0];
            ulonglong2 gBv = *(const ulonglong2*)&gB[kk * 256 + q1];
            unsigned long long wp0 = pk2(w0.x), wp1 = pk2(w0.y),
                               wp2 = pk2(w0.z), wp3 = pk2(w0.w),
                               wp4 = pk2(w1.x), wp5 = pk2(w1.y),
                               wp6 = pk2(w1.z), wp7 = pk2(w1.w);

            acc[0][0] = fma2(wp0, gA.x, acc[0][0]);
            acc[0][1] = fma2(wp0, gA.y, acc[0][1]);
            acc[0][2] = fma2(wp0, gBv.x, acc[0][2]);
            acc[0][3] = fma2(wp0, gBv.y, acc[0][3]);
            acc[1][0] = fma2(wp1, gA.x, acc[1][0]);
            acc[1][1] = fma2(wp1, gA.y, acc[1][1]);
            acc[1][2] = fma2(wp1, gBv.x, acc[1][2]);
            acc[1][3] = fma2(wp1, gBv.y, acc[1][3]);
            acc[2][0] = fma2(wp2, gA.x, acc[2][0]);
            acc[2][1] = fma2(wp2, gA.y, acc[2][1]);
            acc[2][2] = fma2(wp2, gBv.x, acc[2][2]);
            acc[2][3] = fma2(wp2, gBv.y, acc[2][3]);
            acc[3][0] = fma2(wp3, gA.x, acc[3][0]);
            acc[3][1] = fma2(wp3, gA.y, acc[3][1]);
            acc[3][2] = fma2(wp3, gBv.x, acc[3][2]);
            acc[3][3] = fma2(wp3, gBv.y, acc[3][3]);
            acc[4][0] = fma2(wp4, gA.x, acc[4][0]);
            acc[4][1] = fma2(wp4, gA.y, acc[4][1]);
            acc[4][2] = fma2(wp4, gBv.x, acc[4][2]);
            acc[4][3] = fma2(wp4, gBv.y, acc[4][3]);
            acc[5][0] = fma2(wp5, gA.x, acc[5][0]);
            acc[5][1] = fma2(wp5, gA.y, acc[5][1]);
            acc[5][2] = fma2(wp5, gBv.x, acc[5][2]);
            acc[5][3] = fma2(wp5, gBv.y, acc[5][3]);
            acc[6][0] = fma2(wp6, gA.x, acc[6][0]);
            acc[6][1] = fma2(wp6, gA.y, acc[6][1]);
            acc[6][2] = fma2(wp6, gBv.x, acc[6][2]);
            acc[6][3] = fma2(wp6, gBv.y, acc[6][3]);
            acc[7][0] = fma2(wp7, gA.x, acc[7][0]);
            acc[7][1] = fma2(wp7, gA.y, acc[7][1]);
            acc[7][2] = fma2(wp7, gBv.x, acc[7][2]);
            acc[7][3] = fma2(wp7, gBv.y, acc[7][3]);
        }

        if (ph < 3) {
            w_sts(buf ^ 1, wreg);
            cp_wait<0>();
            __syncthreads();
        }
    }

#pragma unroll
    for (int oi = 0; oi < 8; oi++) {
        float* dst = out + ((size_t)b * DIM + (ob + oi)) * HW + p0 + pb;
        ulonglong2 v0, v1;
        v0.x = acc[oi][0]; v0.y = acc[oi][1];
        v1.x = acc[oi][2]; v1.y = acc[oi][3];
        ((ulonglong2*)dst)[0] = v0;
        ((ulonglong2*)dst)[1] = v1;
    }
}

// =====================================================================
// Launch: per-batch pipeline across 3 forked streams (capture-legal
// fork/join DAG).  K1(b) on sA -> K2a(b) on sB -> K2b(b) on sC; batches
// overlap across stages.  Streams/events created once, outside capture
// (first call is the correctness run).
// Inputs: x, gen_kernel, W_in, dw_kernel, lambda_dw, W_out
// =====================================================================
extern "C" void kernel_launch(void* const* d_in, const int* in_sizes, int n_in,
                              void* d_out, int out_size) {
    const float* x     = (const float*)d_in[0];
    const float* genk  = (const float*)d_in[1];
    const float* W_in  = (const float*)d_in[2];
    const float* dwk   = (const float*)d_in[3];
    const float* lam   = (const float*)d_in[4];
    const float* W_out = (const float*)d_in[5];
    float* out = (float*)d_out;

    static int inited = 0;
    static cudaStream_t sA, sB, sC;
    static cudaEvent_t evF, e1[BATCH], e2[BATCH], eA, eB, eC;
    if (!inited) {
        cudaFuncSetAttribute(k_proj_in,  cudaFuncAttributeMaxDynamicSharedMemorySize, 65536);
        cudaFuncSetAttribute(k_proj_out, cudaFuncAttributeMaxDynamicSharedMemorySize, 81920);
        cudaStreamCreateWithFlags(&sA, cudaStreamNonBlocking);
        cudaStreamCreateWithFlags(&sB, cudaStreamNonBlocking);
        cudaStreamCreateWithFlags(&sC, cudaStreamNonBlocking);
        cudaEventCreateWithFlags(&evF, cudaEventDisableTiming);
        cudaEventCreateWithFlags(&eA, cudaEventDisableTiming);
        cudaEventCreateWithFlags(&eB, cudaEventDisableTiming);
        cudaEventCreateWithFlags(&eC, cudaEventDisableTiming);
        for (int i = 0; i < BATCH; i++) {
            cudaEventCreateWithFlags(&e1[i], cudaEventDisableTiming);
            cudaEventCreateWithFlags(&e2[i], cudaEventDisableTiming);
        }
        inited = 1;
    }

    // fork the three worker streams from the origin (capture) stream
    cudaEventRecord(evF, 0);
    cudaStreamWaitEvent(sA, evF, 0);
    cudaStreamWaitEvent(sB, evF, 0);
    cudaStreamWaitEvent(sC, evF, 0);

    dim3 g1(HW / 128, 2, 1);       // 256 CTAs / batch
    dim3 g2(HID, IMG_H / 32, 1);   // 512 CTAs / batch
    dim3 g3(HW / 256, 1, 1);       // 64 CTAs / batch

    for (int b = 0; b < BATCH; b++) {
        k_proj_in<<<g1, 256, 65536, sA>>>(x, W_in, b);
        cudaEventRecord(e1[b], sA);
        cudaStreamWaitEvent(sB, e1[b], 0);
        k_conv_gelu<<<g2, 256, 0, sB>>>(genk, dwk, lam, b);
        cudaEventRecord(e2[b], sB);
        cudaStreamWaitEvent(sC, e2[b], 0);
        k_proj_out<<<g3, 256, 81920, sC>>>(W_out, out, b);
    }

    // join all workers back into the origin stream
    cudaEventRecord(eA, sA);
    cudaEventRecord(eB, sB);
    cudaEventRecord(eC, sC);
    cudaStreamWaitEvent(0, eA, 0);
    cudaStreamWaitEvent(0, eB, 0);
    cudaStreamWaitEvent(0, eC, 0);
}

// round 16
// speedup vs baseline: 1.2561x; 1.2173x over previous
#include <cuda_runtime.h>
#include <math.h>

// Problem constants
#define BATCH 8
#define DIM   64
#define HID   128
#define C2    256      // 2*HID
#define IMG_H 128
#define IMG_W 128
#define HW    16384    // 128*128

// Scratch u, INTERLEAVED: g_u2[b][cp][px] holds pair (u[cp], u[cp+128]).
__device__ float g_u2[(size_t)BATCH * HID * HW * 2];
// Scratch g = gelu(x1)*x2, planar (B, HID, HW) fp32 = 64 MiB.
__device__ float g_g[(size_t)BATCH * HID * HW];

// ---------------- packed f32x2 helpers (sm_103a FFMA2) ----------------
__device__ __forceinline__ unsigned long long pk2(float v) {
    unsigned long long r;
    asm("mov.b64 %0, {%1, %1};" : "=l"(r) : "f"(v));
    return r;
}
__device__ __forceinline__ unsigned long long fma2(unsigned long long a,
                                                   unsigned long long b,
                                                   unsigned long long c) {
    unsigned long long d;
    asm("fma.rn.f32x2 %0, %1, %2, %3;" : "=l"(d) : "l"(a), "l"(b), "l"(c));
    return d;
}
__device__ __forceinline__ void upk(unsigned long long v, float& lo, float& hi) {
    asm("mov.b64 {%0, %1}, %2;" : "=f"(lo), "=f"(hi) : "l"(v));
}

// ---------------- cp.async helpers ----------------
__device__ __forceinline__ void cp16(void* smem_dst, const void* gmem_src, int src_sz) {
    unsigned int s = (unsigned int)__cvta_generic_to_shared(smem_dst);
    asm volatile("cp.async.ca.shared.global [%0], [%1], 16, %2;\n"
                 :: "r"(s), "l"(gmem_src), "r"(src_sz));
}
__device__ __forceinline__ void cp_commit() {
    asm volatile("cp.async.commit_group;\n");
}
template <int N>
__device__ __forceinline__ void cp_wait() {
    asm volatile("cp.async.wait_group %0;\n" :: "n"(N));
}

// 16B-chunk XOR swizzles (conflict-free stride-32B/64B access)
__device__ __forceinline__ int swz4(int c) { return c ^ ((c >> 3) & 3); }  // 512B row
__device__ __forceinline__ int swz8(int c) { return c ^ ((c >> 3) & 7); }  // 1024B+ row

#define AROW 264

// =====================================================================
// STAGE 1 (round-12 k_proj_in body): u = W_in * x, interleaved store.
// l in [0,1024): px-tile = l&127, cp0 = ((l>>7)&1)*64, b = bbase + (l>>8)
// Dynamic smem: 64 KB.
// =====================================================================
__device__ __forceinline__ void stage_k1(int l, int bbase,
                                         const float* __restrict__ x,
                                         const float* __restrict__ W_in) {
    extern __shared__ float dsm[];
    float* xs  = dsm;              // [64][128 swizzled]  32768 B
    float* Wsa = dsm + 8192;       // [64][64]            16384 B
    float* Wsb = dsm + 12288;      // [64][64]            16384 B

    const int t   = threadIdx.x;
    const int p0  = (l & 127) * 128;
    const int cp0 = ((l >> 7) & 1) * 64;
    const int b   = bbase + (l >> 8);

    const int tx = t & 15;
    const int ty = t >> 4;
    const int pb = tx * 8;
    const int q0 = swz4(2 * tx) * 4;
    const int q1 = swz4(2 * tx + 1) * 4;

    // prologue: weight LDGs first (latency overlaps cp.async issue)
    float4 wva[4], wvb[4];
#pragma unroll
    for (int i = 0; i < 4; i++) {
        int idx = t + i * 256;
        int j   = idx & 63;
        int kq  = idx >> 6;
        wva[i] = *(const float4*)&W_in[(cp0 + j) * 64 + kq * 4];
        wvb[i] = *(const float4*)&W_in[(cp0 + 128 + j) * 64 + kq * 4];
    }
    const float* xg = x + ((size_t)b * DIM) * HW + p0;
#pragma unroll
    for (int i = 0; i < 8; i++) {
        int idx = t + i * 256;
        int kk  = idx >> 5;
        int c4  = idx & 31;
        cp16(&xs[(kk * 32 + swz4(c4)) * 4], xg + (size_t)kk * HW + c4 * 4, 16);
    }
    cp_commit();
#pragma unroll
    for (int i = 0; i < 4; i++) {
        int idx = t + i * 256;
        int j   = idx & 63;
        int kq  = idx >> 6;
        Wsa[(kq * 4 + 0) * 64 + j] = wva[i].x;
        Wsa[(kq * 4 + 1) * 64 + j] = wva[i].y;
        Wsa[(kq * 4 + 2) * 64 + j] = wva[i].z;
        Wsa[(kq * 4 + 3) * 64 + j] = wva[i].w;
        Wsb[(kq * 4 + 0) * 64 + j] = wvb[i].x;
        Wsb[(kq * 4 + 1) * 64 + j] = wvb[i].y;
        Wsb[(kq * 4 + 2) * 64 + j] = wvb[i].z;
        Wsb[(kq * 4 + 3) * 64 + j] = wvb[i].w;
    }
    cp_wait<0>();
    __syncthreads();                      // the ONLY barrier

    unsigned long long aa[4][4], ab[4][4];
#pragma unroll
    for (int i = 0; i < 4; i++)
#pragma unroll
        for (int j = 0; j < 4; j++) { aa[i][j] = 0ull; ab[i][j] = 0ull; }

#pragma unroll 8
    for (int kk = 0; kk < 64; kk++) {
        float4 wa = *(const float4*)&Wsa[kk * 64 + 4 * ty];
        float4 wb = *(const float4*)&Wsb[kk * 64 + 4 * ty];
        ulonglong2 xv0 = *(const ulonglong2*)(xs + kk * 128 + q0);
        ulonglong2 xv1 = *(const ulonglong2*)(xs + kk * 128 + q1);
        unsigned long long wa0 = pk2(wa.x), wa1 = pk2(wa.y),
                           wa2 = pk2(wa.z), wa3 = pk2(wa.w);
        unsigned long long wb0 = pk2(wb.x), wb1 = pk2(wb.y),
                           wb2 = pk2(wb.z), wb3 = pk2(wb.w);

        aa[0][0] = fma2(wa0, xv0.x, aa[0][0]);
        aa[0][1] = fma2(wa0, xv0.y, aa[0][1]);
        aa[0][2] = fma2(wa0, xv1.x, aa[0][2]);
        aa[0][3] = fma2(wa0, xv1.y, aa[0][3]);
        aa[1][0] = fma2(wa1, xv0.x, aa[1][0]);
        aa[1][1] = fma2(wa1, xv0.y, aa[1][1]);
        aa[1][2] = fma2(wa1, xv1.x, aa[1][2]);
        aa[1][3] = fma2(wa1, xv1.y, aa[1][3]);
        aa[2][0] = fma2(wa2, xv0.x, aa[2][0]);
        aa[2][1] = fma2(wa2, xv0.y, aa[2][1]);
        aa[2][2] = fma2(wa2, xv1.x, aa[2][2]);
        aa[2][3] = fma2(wa2, xv1.y, aa[2][3]);
        aa[3][0] = fma2(wa3, xv0.x, aa[3][0]);
        aa[3][1] = fma2(wa3, xv0.y, aa[3][1]);
        aa[3][2] = fma2(wa3, xv1.x, aa[3][2]);
        aa[3][3] = fma2(wa3, xv1.y, aa[3][3]);

        ab[0][0] = fma2(wb0, xv0.x, ab[0][0]);
        ab[0][1] = fma2(wb0, xv0.y, ab[0][1]);
        ab[0][2] = fma2(wb0, xv1.x, ab[0][2]);
        ab[0][3] = fma2(wb0, xv1.y, ab[0][3]);
        ab[1][0] = fma2(wb1, xv0.x, ab[1][0]);
        ab[1][1] = fma2(wb1, xv0.y, ab[1][1]);
        ab[1][2] = fma2(wb1, xv1.x, ab[1][2]);
        ab[1][3] = fma2(wb1, xv1.y, ab[1][3]);
        ab[2][0] = fma2(wb2, xv0.x, ab[2][0]);
        ab[2][1] = fma2(wb2, xv0.y, ab[2][1]);
        ab[2][2] = fma2(wb2, xv1.x, ab[2][2]);
        ab[2][3] = fma2(wb2, xv1.y, ab[2][3]);
        ab[3][0] = fma2(wb3, xv0.x, ab[3][0]);
        ab[3][1] = fma2(wb3, xv0.y, ab[3][1]);
        ab[3][2] = fma2(wb3, xv1.x, ab[3][2]);
        ab[3][3] = fma2(wb3, xv1.y, ab[3][3]);
    }

#pragma unroll
    for (int ci = 0; ci < 4; ci++) {
        int cp = cp0 + 4 * ty + ci;
        float* base = g_u2 + (((size_t)b * HID + cp) * HW + p0 + pb) * 2;
#pragma unroll
        for (int j = 0; j < 4; j++) {
            float alo, ahi, blo, bhi;
            upk(aa[ci][j], alo, ahi);
            upk(ab[ci][j], blo, bhi);
            *(float4*)(base + 4 * j) = make_float4(alo, blo, ahi, bhi);
        }
    }
}

// =====================================================================
// STAGE 2a (round-12 k_conv_gelu body): depthwise 3x3 + GELU gate -> g.
// l in [0,2048): cp = l&127, rb = (l>>7)&3, b = bbase + (l>>9)
// Dynamic smem usage: 35976 B.
// =====================================================================
__device__ __forceinline__ void stage_k2a(int l, int bbase,
                                          const float* __restrict__ genk,
                                          const float* __restrict__ dwkg,
                                          const float* __restrict__ lam) {
    extern __shared__ float dsm[];
    float* halo  = dsm;                    // 34*AROW floats
    float* kc2s  = dsm + 34 * AROW;        // 18 floats

    const int t  = threadIdx.x;
    const int cp = l & 127;
    const int rb = (l >> 7) & 3;
    const int b  = bbase + (l >> 9);
    const int y0 = rb * 32;

    if (t < 18) {
        int tap = t >> 1, br = t & 1;
        int c = cp + br * HID;
        kc2s[tap * 2 + br] = dwkg[c * 9 + tap] + lam[c] * genk[b * (C2 * 9) + c * 9 + tap];
    }
    for (int i = t; i < 272; i += 256) {
        int rr = i >> 3, j = i & 7;
        halo[rr * AROW + ((j < 4) ? j : (256 + j))] = 0.0f;
    }
    {
        const float* src0 = g_u2 + ((size_t)b * HID + cp) * HW * 2;
#pragma unroll
        for (int i = 0; i < 9; i++) {
            int idx = t + i * 256;
            if (idx < 2176) {
                int rr = idx >> 6, ch = idx & 63;
                int gy = y0 - 1 + rr;
                bool ok = (unsigned)gy < 128u;
                cp16(&halo[rr * AROW + swz8(1 + ch) * 4],
                     src0 + (size_t)(ok ? gy : 0) * 256 + ch * 4, ok ? 16 : 0);
            }
        }
        cp_commit();
    }
    cp_wait<0>();
    __syncthreads();

    unsigned long long tap[9];
#pragma unroll
    for (int i = 0; i < 9; i++) tap[i] = *(const unsigned long long*)&kc2s[2 * i];

    const int s  = t & 15;
    const int x0 = s * 8;
    const int yb = t >> 4;
    int qof[6];
#pragma unroll
    for (int j = 0; j < 6; j++) qof[j] = swz8(4 * s + j) * 4;

    float* gbase = g_g + ((size_t)b * HID + cp) * HW;

#pragma unroll
    for (int half = 0; half < 2; half++) {
        int y = yb + half * 16;
        unsigned long long v[8];
#pragma unroll
        for (int j = 0; j < 8; j++) v[j] = 0ull;

#pragma unroll
        for (int r = 0; r < 3; r++) {
            const float* Hrow = &halo[(y + r) * AROW];
            unsigned long long p[12];
#pragma unroll
            for (int j = 0; j < 6; j++) {
                ulonglong2 qq = *(const ulonglong2*)&Hrow[qof[j]];
                p[2 * j]     = qq.x;
                p[2 * j + 1] = qq.y;
            }
#pragma unroll
            for (int dx = 0; dx < 3; dx++) {
                unsigned long long tp_ = tap[r * 3 + dx];
#pragma unroll
                for (int j = 0; j < 8; j++)
                    v[j] = fma2(tp_, p[j + dx + 1], v[j]);
            }
        }
        float o8[8];
#pragma unroll
        for (int j = 0; j < 8; j++) {
            float va, vb;
            upk(v[j], va, vb);
            o8[j] = 0.5f * va * (1.0f + erff(va * 0.7071067811865476f)) * vb;
        }
        float* dst = gbase + (y0 + y) * IMG_W + x0;
        *(float4*)dst       = make_float4(o8[0], o8[1], o8[2], o8[3]);
        *(float4*)(dst + 4) = make_float4(o8[4], o8[5], o8[6], o8[7]);
    }
}

// =====================================================================
// STAGE 2b (round-12 k_proj_out body): out = W_out * g.
// l in [0,256): px-tile = l&63, b = bbase + (l>>6)
// Dynamic smem: 80 KB.
// =====================================================================
__device__ __forceinline__ void stage_k2b(int l, int bbase,
                                          const float* __restrict__ W_out,
                                          float* __restrict__ out) {
    extern __shared__ float dsm[];
    float* gsT = dsm;              // [2][32*256 swizzled]  65536 B
    float* Wo  = dsm + 16384;      // [2][32*64]            16384 B

    const int t  = threadIdx.x;
    const int p0 = (l & 63) * 256;
    const int b  = bbase + (l >> 6);

    const int tx = t & 31;
    const int ty = t >> 5;
    const int pb = tx * 8;
    const int ob = ty * 8;
    const int q0 = swz8(2 * tx) * 4;
    const int q1 = swz8(2 * tx + 1) * 4;

    const float* gb = g_g + ((size_t)b * HID) * HW;

    auto stage_g = [&](int ph, int buf) {
        float* dstb = gsT + buf * 8192;
#pragma unroll
        for (int i = 0; i < 8; i++) {
            int idx = t + i * 256;
            int kk = idx >> 6, ch = idx & 63;
            cp16(&dstb[(kk * 64 + swz8(ch)) * 4],
                 gb + (size_t)(ph * 32 + kk) * HW + p0 + ch * 4, 16);
        }
        cp_commit();
    };
    auto w_ldg = [&](int ph, float* w8) {
#pragma unroll
        for (int i = 0; i < 8; i++) {
            int idx = t + i * 256;
            int kk = idx >> 6, o = idx & 63;
            w8[i] = W_out[o * HID + ph * 32 + kk];
        }
    };
    auto w_sts = [&](int buf, const float* w8) {
        float* dstb = Wo + buf * 2048;
#pragma unroll
        for (int i = 0; i < 8; i++) {
            int idx = t + i * 256;
            int kk = idx >> 6, o = idx & 63;
            dstb[kk * 64 + o] = w8[i];
        }
    };

    unsigned long long acc[8][4];
#pragma unroll
    for (int i = 0; i < 8; i++)
#pragma unroll
        for (int j = 0; j < 4; j++) acc[i][j] = 0ull;

    float wreg[8];
    stage_g(0, 0);
    w_ldg(0, wreg);
    w_sts(0, wreg);
    cp_wait<0>();
    __syncthreads();

#pragma unroll 1
    for (int ph = 0; ph < 4; ph++) {
        const int buf = ph & 1;
        if (ph < 3) {
            stage_g(ph + 1, buf ^ 1);
            w_ldg(ph + 1, wreg);
        }

        const float* gB = gsT + buf * 8192;
        const float* wB = Wo + buf * 2048;
#pragma unroll 8
        for (int kk = 0; kk < 32; kk++) {
            float4 w0 = *(const float4*)&wB[kk * 64 + ob];
            float4 w1 = *(const float4*)&wB[kk * 64 + ob + 4];
            ulonglong2 gA  = *(const ulonglong2*)&gB[kk * 256 + q0];
            ulonglong2 gBv = *(const ulonglong2*)&gB[kk * 256 + q1];
            unsigned long long wp0 = pk2(w0.x), wp1 = pk2(w0.y),
                               wp2 = pk2(w0.z), wp3 = pk2(w0.w),
                               wp4 = pk2(w1.x), wp5 = pk2(w1.y),
                               wp6 = pk2(w1.z), wp7 = pk2(w1.w);

            acc[0][0] = fma2(wp0, gA.x, acc[0][0]);
            acc[0][1] = fma2(wp0, gA.y, acc[0][1]);
            acc[0][2] = fma2(wp0, gBv.x, acc[0][2]);
            acc[0][3] = fma2(wp0, gBv.y, acc[0][3]);
            acc[1][0] = fma2(wp1, gA.x, acc[1][0]);
            acc[1][1] = fma2(wp1, gA.y, acc[1][1]);
            acc[1][2] = fma2(wp1, gBv.x, acc[1][2]);
            acc[1][3] = fma2(wp1, gBv.y, acc[1][3]);
            acc[2][0] = fma2(wp2, gA.x, acc[2][0]);
            acc[2][1] = fma2(wp2, gA.y, acc[2][1]);
            acc[2][2] = fma2(wp2, gBv.x, acc[2][2]);
            acc[2][3] = fma2(wp2, gBv.y, acc[2][3]);
            acc[3][0] = fma2(wp3, gA.x, acc[3][0]);
            acc[3][1] = fma2(wp3, gA.y, acc[3][1]);
            acc[3][2] = fma2(wp3, gBv.x, acc[3][2]);
            acc[3][3] = fma2(wp3, gBv.y, acc[3][3]);
            acc[4][0] = fma2(wp4, gA.x, acc[4][0]);
            acc[4][1] = fma2(wp4, gA.y, acc[4][1]);
            acc[4][2] = fma2(wp4, gBv.x, acc[4][2]);
            acc[4][3] = fma2(wp4, gBv.y, acc[4][3]);
            acc[5][0] = fma2(wp5, gA.x, acc[5][0]);
            acc[5][1] = fma2(wp5, gA.y, acc[5][1]);
            acc[5][2] = fma2(wp5, gBv.x, acc[5][2]);
            acc[5][3] = fma2(wp5, gBv.y, acc[5][3]);
            acc[6][0] = fma2(wp6, gA.x, acc[6][0]);
            acc[6][1] = fma2(wp6, gA.y, acc[6][1]);
            acc[6][2] = fma2(wp6, gBv.x, acc[6][2]);
            acc[6][3] = fma2(wp6, gBv.y, acc[6][3]);
            acc[7][0] = fma2(wp7, gA.x, acc[7][0]);
            acc[7][1] = fma2(wp7, gA.y, acc[7][1]);
            acc[7][2] = fma2(wp7, gBv.x, acc[7][2]);
            acc[7][3] = fma2(wp7, gBv.y, acc[7][3]);
        }

        if (ph < 3) {
            w_sts(buf ^ 1, wreg);
            cp_wait<0>();
            __syncthreads();
        }
    }

#pragma unroll
    for (int oi = 0; oi < 8; oi++) {
        float* dst = out + ((size_t)b * DIM + (ob + oi)) * HW + p0 + pb;
        ulonglong2 v0, v1;
        v0.x = acc[oi][0]; v0.y = acc[oi][1];
        v1.x = acc[oi][2]; v1.y = acc[oi][3];
        ((ulonglong2*)dst)[0] = v0;
        ((ulonglong2*)dst)[1] = v1;
    }
}

// =====================================================================
// Pipeline kernels (single stream, CTA-range fusion of independent
// stages — co-residency within one launch, no stream/event machinery)
// =====================================================================
__global__ void __launch_bounds__(256, 2) kP1(const float* __restrict__ x,
                                              const float* __restrict__ W_in) {
    stage_k1(blockIdx.x, 0, x, W_in);
}
__global__ void __launch_bounds__(256, 2) kP2(const float* __restrict__ x,
                                              const float* __restrict__ W_in,
                                              const float* __restrict__ genk,
                                              const float* __restrict__ dwkg,
                                              const float* __restrict__ lam) {
    if (blockIdx.x < 1024) stage_k1(blockIdx.x, 4, x, W_in);
    else                   stage_k2a(blockIdx.x - 1024, 0, genk, dwkg, lam);
}
__global__ void __launch_bounds__(256, 2) kP3(const float* __restrict__ genk,
                                              const float* __restrict__ dwkg,
                                              const float* __restrict__ lam,
                                              const float* __restrict__ W_out,
                                              float* __restrict__ out) {
    if (blockIdx.x < 256) stage_k2b(blockIdx.x, 0, W_out, out);
    else                  stage_k2a(blockIdx.x - 256, 4, genk, dwkg, lam);
}
__global__ void __launch_bounds__(256, 2) kP4(const float* __restrict__ W_out,
                                              float* __restrict__ out) {
    stage_k2b(blockIdx.x, 4, W_out, out);
}

// =====================================================================
// Launch (graph-capturable, no allocs, single stream)
// Inputs: x, gen_kernel, W_in, dw_kernel, lambda_dw, W_out
// =====================================================================
extern "C" void kernel_launch(void* const* d_in, const int* in_sizes, int n_in,
                              void* d_out, int out_size) {
    const float* x     = (const float*)d_in[0];
    const float* genk  = (const float*)d_in[1];
    const float* W_in  = (const float*)d_in[2];
    const float* dwk   = (const float*)d_in[3];
    const float* lam   = (const float*)d_in[4];
    const float* W_out = (const float*)d_in[5];
    float* out = (float*)d_out;

    static int attr_done = 0;
    if (!attr_done) {
        cudaFuncSetAttribute(kP1, cudaFuncAttributeMaxDynamicSharedMemorySize, 65536);
        cudaFuncSetAttribute(kP2, cudaFuncAttributeMaxDynamicSharedMemorySize, 65536);
        cudaFuncSetAttribute(kP3, cudaFuncAttributeMaxDynamicSharedMemorySize, 81920);
        cudaFuncSetAttribute(kP4, cudaFuncAttributeMaxDynamicSharedMemorySize, 81920);
        attr_done = 1;
    }

    kP1<<<1024, 256, 65536>>>(x, W_in);                    // K1(b0-3)
    kP2<<<3072, 256, 65536>>>(x, W_in, genk, dwk, lam);    // K1(b4-7) || K2a(b0-3)
    kP3<<<2304, 256, 81920>>>(genk, dwk, lam, W_out, out); // K2b(b0-3) || K2a(b4-7)
    kP4<<<256,  256, 81920>>>(W_out, out);                 // K2b(b4-7)
}